// round 16
// baseline (speedup 1.0000x reference)
#include <cuda_runtime.h>
#include <cstdint>

#define B_ 4
#define L_ 512
#define D_ 256
#define U_ 64
#define TI 8
#define TJ 64
#define NTROW (L_/TI)

// scratch for projections (allowed: __device__ globals, no allocation)
__device__ float g_q[B_*L_*U_];
__device__ float g_k[B_*L_*U_];

__device__ __forceinline__ float tanh_ap(float x){ float y; asm("tanh.approx.f32 %0, %1;" : "=f"(y) : "f"(x)); return y; }
__device__ __forceinline__ float ex2_ap(float x){ float y; asm("ex2.approx.f32 %0, %1;" : "=f"(y) : "f"(x)); return y; }
__device__ __forceinline__ unsigned long long dup2(float x){
    unsigned long long r; asm("mov.b64 %0, {%1, %1};" : "=l"(r) : "f"(x)); return r;
}
__device__ __forceinline__ void fma2(unsigned long long &a, unsigned long long x, unsigned long long y){
    asm("fma.rn.f32x2 %0, %1, %2, %0;" : "+l"(a) : "l"(x), "l"(y));
}
__device__ __forceinline__ void mul2(unsigned long long &a, unsigned long long x){
    asm("mul.rn.f32x2 %0, %0, %1;" : "+l"(a) : "l"(x));
}
__device__ __forceinline__ float2 unpack2(unsigned long long v){
    float lo, hi; asm("mov.b64 {%0, %1}, %2;" : "=f"(lo), "=f"(hi) : "l"(v)); return make_float2(lo, hi);
}
__device__ __forceinline__ unsigned smem_u32(const void* p){
    return (unsigned)__cvta_generic_to_shared(p);
}
__device__ __forceinline__ void cp16(unsigned dst, const void* src){
    asm volatile("cp.async.cg.shared.global [%0], [%1], 16;" :: "r"(dst), "l"(src));
}
__device__ __forceinline__ void cp_commit(){ asm volatile("cp.async.commit_group;"); }
__device__ __forceinline__ void cp_wait0(){ asm volatile("cp.async.wait_group 0;"); }
__device__ __forceinline__ void cp_wait1(){ asm volatile("cp.async.wait_group 1;"); }
__device__ __forceinline__ void barg(int id){ asm volatile("bar.sync %0, 256;" :: "r"(id) : "memory"); }

// ---------------------------------------------------------------------------
// Phase 1 (unchanged from R14/R15 -- measured): q = X@Wt ; k = X@Wx + bh.
// 256 blocks x 128 threads, 16 rows/block; W in two 32KB static-smem halves;
// X direct LDG.128.
// ---------------------------------------------------------------------------
__global__ void __launch_bounds__(128) proj_kernel(
    const float* __restrict__ X, const float* __restrict__ Wt,
    const float* __restrict__ Wx, const float* __restrict__ bh)
{
    __shared__ __align__(16) float W_s[128*U_];   // 32KB (half of W)

    const int bid  = blockIdx.x;
    const bool is_k = bid >= 128;
    const int rb   = bid & 127;
    const float* __restrict__ W = is_k ? Wx : Wt;
    const int t    = threadIdx.x;
    const int row0 = rb * 16;

    const int quad = t & 15;
    const int rg   = t >> 4;

    const float4* __restrict__ Xa = reinterpret_cast<const float4*>(X + (row0+rg  )*D_);
    const float4* __restrict__ Xb = reinterpret_cast<const float4*>(X + (row0+rg+8)*D_);
    const float4* __restrict__ W4 = reinterpret_cast<const float4*>(W);

    unsigned long long a01_0 = 0ull, a23_0 = 0ull;
    unsigned long long a01_1 = 0ull, a23_1 = 0ull;

    #pragma unroll
    for (int half = 0; half < 2; ++half) {
        __syncthreads();
        #pragma unroll
        for (int i = 0; i < 16; ++i)
            reinterpret_cast<float4*>(W_s)[t + i*128] = W4[half*2048 + t + i*128];
        __syncthreads();

        const int dbase = half * 32;
        #pragma unroll 4
        for (int d4 = 0; d4 < 32; ++d4) {
            float4 xa = Xa[dbase + d4];
            float4 xb = Xb[dbase + d4];
            const float* xaf = reinterpret_cast<const float*>(&xa);
            const float* xbf = reinterpret_cast<const float*>(&xb);
            #pragma unroll
            for (int c = 0; c < 4; ++c) {
                ulonglong2 w2 = *reinterpret_cast<const ulonglong2*>(W_s + (d4*4+c)*U_ + quad*4);
                unsigned long long xx0 = dup2(xaf[c]);
                unsigned long long xx1 = dup2(xbf[c]);
                fma2(a01_0, xx0, w2.x);
                fma2(a23_0, xx0, w2.y);
                fma2(a01_1, xx1, w2.x);
                fma2(a23_1, xx1, w2.y);
            }
        }
    }

    float bx = 0.f, by = 0.f, bz = 0.f, bw = 0.f;
    if (is_k) { bx = bh[quad*4+0]; by = bh[quad*4+1]; bz = bh[quad*4+2]; bw = bh[quad*4+3]; }

    float* base = (is_k ? g_k : g_q);
    {
        float2 v01 = unpack2(a01_0), v23 = unpack2(a23_0);
        float4 o; o.x = v01.x+bx; o.y = v01.y+by; o.z = v23.x+bz; o.w = v23.y+bw;
        *reinterpret_cast<float4*>(base + (row0 + rg)*U_ + quad*4) = o;
    }
    {
        float2 v01 = unpack2(a01_1), v23 = unpack2(a23_1);
        float4 o; o.x = v01.x+bx; o.y = v01.y+by; o.z = v23.x+bz; o.w = v23.y+bw;
        *reinterpret_cast<float4*>(base + (row0 + rg + 8)*U_ + quad*4) = o;
    }
}

// ---------------------------------------------------------------------------
// Phase 2: split-KV dual-group attention, TJ=64, 2 barriers/tile.
// 128 CTAs x 512 threads. Pair {A=pr, B=63-pr}; 9 TJ=64 jobs split 5/4.
// Choreography: wait(k) -> barg -> commit X(n)+k(n+1) -> score (X hides here)
//               -> store p -> wait(X) -> barg -> PV.
// PV: thread <-> d-column; acc[k] = packed (v[2k][d], v[2k+1][d]);
//     p transposed in smem (stride 12) -> 2 LDS.128 give all 4 row-pairs.
// ---------------------------------------------------------------------------
#define GRP_B (32768 + 65536)      // kbuf 2x16KB + Xs 64KB

__global__ void __launch_bounds__(512, 1) attn_kernel(
    const float* __restrict__ X, const float* __restrict__ Wa,
    float* __restrict__ out)
{
    extern __shared__ __align__(16) unsigned char smem_raw[];

    const int t    = threadIdx.x;
    const int g    = t >> 8;           // group 0/1
    const int tl   = t & 255;          // thread-in-group
    const int lane = t & 31;
    const int wl   = (t >> 5) & 7;     // warp-in-group = row
    const int b    = blockIdx.x >> 5;
    const int pr   = blockIdx.x & 31;

    const int i0A  = pr * TI;
    const int i0B  = (63 - pr) * TI;
    const int ntjA = pr/8 + 1;             // A tiles (1..4)
    const int sB   = 5 - ntjA;             // group0's B tiles [0, sB)
    const int njobs = g ? 4 : 5;

    unsigned char* grp = smem_raw + g*GRP_B;
    float4* kbuf = reinterpret_cast<float4*>(grp);                 // 2x16KB
    float*  Xs   = reinterpret_cast<float*>(grp + 32768);          // 64KB [j][d]
    unsigned char* tail = smem_raw + 2*GRP_B;
    float4* q_all  = reinterpret_cast<float4*>(tail);              // 4KB
    float4* wa4    = reinterpret_cast<float4*>(tail + 4096);       // 256B
    float*  p2T    = reinterpret_cast<float*>(tail + 4352) + g*768;   // [j][row] stride 12, 2x3KB
    float*  alpha_s= reinterpret_cast<float*>(tail + 10496) + g*8;
    float*  sinv   = reinterpret_cast<float*>(tail + 10560) + g*8;
    float*  paccb  = reinterpret_cast<float*>(tail + 10624);       // [g][8][256] 2x8KB
    float*  pacc   = paccb + g*2048;
    float*  pmb    = reinterpret_cast<float*>(tail + 27008);       // [g][8]
    float*  psb    = pmb + 16;
    float*  pm     = pmb + g*8;
    float*  ps     = psb + g*8;

    const float* __restrict__ Xb = X   + b*L_*D_;
    const float* __restrict__ kb = g_k + b*L_*U_;
    const float* __restrict__ qb = g_q + b*L_*U_;

    if (t < U_) reinterpret_cast<float*>(wa4)[t] = Wa[t] * 1.4426950408889634f;
    if (t < 256) {                         // q for both row-tiles (16 rows)
        int rt = t >> 7, idx = t & 127;
        int i = idx >> 4, uq = idx & 15;
        int gr = (rt ? i0B : i0A) + i;
        q_all[rt*128 + uq*8 + i] = *reinterpret_cast<const float4*>(qb + gr*U_ + uq*4);
    }

    // cp.async targets
    const unsigned k_base = smem_u32(kbuf);
    const unsigned x_dst0 = smem_u32(Xs) + tl*16;
    const unsigned KBUF_B = 1024*16;   // 16KB per buffer

    const int bid_bar = 1 + g;

    // prologue: prefetch k(job 0) into buffer 0
    {
        const int j0p = g ? sB*TJ : 0;
        #pragma unroll
        for (int rep = 0; rep < 4; ++rep) {
            int idx = tl + rep*256;
            int uq = idx & 15, j = idx >> 4;
            cp16(k_base + (uq*TJ + j)*16, kb + (j0p + j)*U_ + uq*4);
        }
        cp_commit();
    }
    __syncthreads();   // wa4 + q_all visible CTA-wide

    float m_run = -1e30f, s_run = 0.f;
    unsigned long long acc[4] = {0ull, 0ull, 0ull, 0ull};

    for (int n = 0; n < njobs; ++n) {
        // decode job -> (row-tile rt, j0)
        int rt, j0;
        if (g == 0) {
            if (n < ntjA) { rt = 0; j0 = n*TJ; }
            else          { rt = 1; j0 = (n - ntjA)*TJ; }
        } else            { rt = 1; j0 = (sB + n)*TJ; }
        const int cur = n & 1;
        const bool more = (n + 1 < njobs);

        cp_wait0();      // k(n) landed (only k pending at loop top)
        barg(bid_bar);   // k(n) visible + prev PV done reading Xs/p2T

        // commit X(n) fill (64KB: 16 cp16/thread) -- hides under score below
        #pragma unroll
        for (int rep = 0; rep < 16; ++rep) {
            int idx = tl + rep*256;
            cp16(x_dst0 + rep*4096, Xb + (j0 + (idx>>6))*D_ + (idx&63)*4);
        }
        cp_commit();
        // commit k(n+1) fill
        if (more) {
            int j0n;
            if (g == 0) j0n = (n+1 < ntjA) ? (n+1)*TJ : (n+1-ntjA)*TJ;
            else        j0n = (sB + n + 1)*TJ;
            const unsigned off = ((n+1) & 1)*KBUF_B;
            #pragma unroll
            for (int rep = 0; rep < 4; ++rep) {
                int idx = tl + rep*256;
                int uq = idx & 15, j = idx >> 4;
                cp16(k_base + off + (uq*TJ + j)*16, kb + (j0n + j)*U_ + uq*4);
            }
            cp_commit();
        }

        // ---- score: rows wl, j = j0+lane and j0+lane+32, log2 domain ----
        const int gi = (rt ? i0B : i0A) + wl;
        const float4* kc = kbuf + cur*1024;
        const float4* qr = q_all + rt*128;
        float e0 = 0.f, e1 = 0.f, e2 = 0.f, e3 = 0.f;
        #pragma unroll
        for (int uq = 0; uq < 16; ++uq) {
            float4 kv0 = kc[uq*TJ + lane];        // conflict-free
            float4 kv1 = kc[uq*TJ + lane + 32];   // conflict-free
            float4 qv  = qr[uq*8 + wl];           // broadcast
            float4 wa  = wa4[uq];                 // broadcast
            e0 += wa.x * tanh_ap(qv.x + kv0.x);
            e1 += wa.y * tanh_ap(qv.y + kv0.y);
            e0 += wa.z * tanh_ap(qv.z + kv0.z);
            e1 += wa.w * tanh_ap(qv.w + kv0.w);
            e2 += wa.x * tanh_ap(qv.x + kv1.x);
            e3 += wa.y * tanh_ap(qv.y + kv1.y);
            e2 += wa.z * tanh_ap(qv.z + kv1.z);
            e3 += wa.w * tanh_ap(qv.w + kv1.w);
        }
        float eA = e0 + e1;
        float eB = e2 + e3;
        if (j0 + lane      > gi) eA = -1e30f;   // causal: exp2 -> exact 0
        if (j0 + lane + 32 > gi) eB = -1e30f;

        // ---- max reduce + p (sum deferred past barrier) ----
        float mt = fmaxf(eA, eB);
        #pragma unroll
        for (int off = 16; off; off >>= 1)
            mt = fmaxf(mt, __shfl_xor_sync(0xffffffffu, mt, off));
        float m_new = fmaxf(m_run, mt);
        float p0 = ex2_ap(eA - m_new);
        float p1 = ex2_ap(eB - m_new);
        float alpha = ex2_ap(m_run - m_new);
        p2T[lane*12 + wl]        = p0;   // transposed store (4-way conflict)
        p2T[(lane+32)*12 + wl]   = p1;
        if (lane == 0) alpha_s[wl] = alpha;

        if (more) cp_wait1(); else cp_wait0();   // X(n) landed (k(n+1) may pend)
        barg(bid_bar);                           // X + p2T + alpha visible

        // deferred sum reduction (overlaps PV issue below)
        float st = p0 + p1;
        #pragma unroll
        for (int off = 16; off; off >>= 1)
            st += __shfl_xor_sync(0xffffffffu, st, off);
        s_run = s_run * alpha + st;
        m_run = m_new;

        // ---- PV: thread = d-column tl; acc[k] = (v[2k][d], v[2k+1][d]) ----
        {
            const unsigned long long* al2 =
                reinterpret_cast<const unsigned long long*>(alpha_s);
            mul2(acc[0], al2[0]);
            mul2(acc[1], al2[1]);
            mul2(acc[2], al2[2]);
            mul2(acc[3], al2[3]);
        }
        const float* xsp = Xs + tl;
        #pragma unroll 8
        for (int j = 0; j < TJ; ++j) {
            unsigned long long xx = dup2(xsp[j*D_]);     // LDS.32 coalesced
            ulonglong2 pA = *reinterpret_cast<const ulonglong2*>(p2T + j*12);     // rows 0-3
            ulonglong2 pB = *reinterpret_cast<const ulonglong2*>(p2T + j*12 + 4); // rows 4-7
            fma2(acc[0], xx, pA.x);
            fma2(acc[1], xx, pA.y);
            fma2(acc[2], xx, pB.x);
            fma2(acc[3], xx, pB.y);
        }

        // ---- segment boundaries ----
        const bool direct = (g == 0) && (n + 1 == ntjA);
        if (direct) {
            if (lane == 0) sinv[wl] = 1.0f / s_run;
            barg(bid_bar);              // sinv visible (only on the direct tile)
            #pragma unroll
            for (int k = 0; k < 4; ++k) {
                float2 v = unpack2(acc[k]);
                out[(b*L_ + i0A + 2*k    )*D_ + tl] = v.x * sinv[2*k];
                out[(b*L_ + i0A + 2*k + 1)*D_ + tl] = v.y * sinv[2*k+1];
                acc[k] = 0ull;
            }
            m_run = -1e30f; s_run = 0.f;
        } else if (n + 1 == njobs) {
            // flush B partial (unnormalized acc + m,s) for merge
            if (lane == 0) { pm[wl] = m_run; ps[wl] = s_run; }
            #pragma unroll
            for (int k = 0; k < 4; ++k) {
                float2 v = unpack2(acc[k]);
                pacc[(2*k    )*D_ + tl] = v.x;
                pacc[(2*k + 1)*D_ + tl] = v.y;
            }
        }
        // next iteration's top barg orders Xs/p2T reuse
    }

    // ---- merge the two B partials (flash-decoding combine) ----
    __syncthreads();
    {
        const int r  = t >> 6;   // 0..7
        const int dq = t & 63;   // d-quad
        float m0 = pmb[r],  m1 = pmb[8 + r];
        float s0 = psb[r],  s1 = psb[8 + r];
        float M  = fmaxf(m0, m1);
        float w0 = ex2_ap(m0 - M), w1 = ex2_ap(m1 - M);
        float dn = 1.0f / (w0*s0 + w1*s1);
        float4 a0 = *reinterpret_cast<float4*>(&paccb[r*D_ + dq*4]);
        float4 a1 = *reinterpret_cast<float4*>(&paccb[2048 + r*D_ + dq*4]);
        float4 o;
        o.x = (w0*a0.x + w1*a1.x)*dn;
        o.y = (w0*a0.y + w1*a1.y)*dn;
        o.z = (w0*a0.z + w1*a1.z)*dn;
        o.w = (w0*a0.w + w1*a1.w)*dn;
        *reinterpret_cast<float4*>(out + (b*L_ + i0B + r)*D_ + dq*4) = o;
    }
}

// ---------------------------------------------------------------------------
extern "C" void kernel_launch(void* const* d_in, const int* in_sizes, int n_in,
                              void* d_out, int out_size)
{
    const float* X  = (const float*)d_in[0];
    const float* Wt = (const float*)d_in[1];
    const float* Wx = (const float*)d_in[2];
    const float* bh = (const float*)d_in[3];
    const float* Wa = (const float*)d_in[4];
    // d_in[5] = ba : constant shift inside softmax -> mathematically a no-op

    const int attn_smem = 2*GRP_B + 27136;   // ~218.5KB
    cudaFuncSetAttribute(attn_kernel, cudaFuncAttributeMaxDynamicSharedMemorySize, attn_smem);

    proj_kernel<<<256, 128>>>(X, Wt, Wx, bh);
    attn_kernel<<<B_*(NTROW/2), 512, attn_smem>>>(X, Wa, (float*)d_out);
}

// round 17
// speedup vs baseline: 1.0922x; 1.0922x over previous
#include <cuda_runtime.h>
#include <cstdint>

#define B_ 4
#define L_ 512
#define D_ 256
#define U_ 64
#define TI 8
#define TJ 64
#define NTROW (L_/TI)

// scratch for projections (allowed: __device__ globals, no allocation)
__device__ float g_q[B_*L_*U_];
__device__ float g_k[B_*L_*U_];

__device__ __forceinline__ float tanh_ap(float x){ float y; asm("tanh.approx.f32 %0, %1;" : "=f"(y) : "f"(x)); return y; }
__device__ __forceinline__ float ex2_ap(float x){ float y; asm("ex2.approx.f32 %0, %1;" : "=f"(y) : "f"(x)); return y; }
__device__ __forceinline__ unsigned long long dup2(float x){
    unsigned long long r; asm("mov.b64 %0, {%1, %1};" : "=l"(r) : "f"(x)); return r;
}
__device__ __forceinline__ void fma2(unsigned long long &a, unsigned long long x, unsigned long long y){
    asm("fma.rn.f32x2 %0, %1, %2, %0;" : "+l"(a) : "l"(x), "l"(y));
}
__device__ __forceinline__ void mul2(unsigned long long &a, unsigned long long x){
    asm("mul.rn.f32x2 %0, %0, %1;" : "+l"(a) : "l"(x));
}
__device__ __forceinline__ float2 unpack2(unsigned long long v){
    float lo, hi; asm("mov.b64 {%0, %1}, %2;" : "=f"(lo), "=f"(hi) : "l"(v)); return make_float2(lo, hi);
}
__device__ __forceinline__ unsigned smem_u32(const void* p){
    return (unsigned)__cvta_generic_to_shared(p);
}
__device__ __forceinline__ void cp16(unsigned dst, const void* src){
    asm volatile("cp.async.cg.shared.global [%0], [%1], 16;" :: "r"(dst), "l"(src));
}
__device__ __forceinline__ void cp_commit(){ asm volatile("cp.async.commit_group;"); }
__device__ __forceinline__ void cp_wait0(){ asm volatile("cp.async.wait_group 0;"); }
__device__ __forceinline__ void cp_wait1(){ asm volatile("cp.async.wait_group 1;"); }
__device__ __forceinline__ void barg(int id){ asm volatile("bar.sync %0, 256;" :: "r"(id) : "memory"); }

// ---------------------------------------------------------------------------
// Phase 1 (unchanged -- measured): q = X@Wt ; k = X@Wx + bh.
// 256 blocks x 128 threads, 16 rows/block; W in two 32KB static-smem halves;
// X direct LDG.128.
// ---------------------------------------------------------------------------
__global__ void __launch_bounds__(128) proj_kernel(
    const float* __restrict__ X, const float* __restrict__ Wt,
    const float* __restrict__ Wx, const float* __restrict__ bh)
{
    __shared__ __align__(16) float W_s[128*U_];   // 32KB (half of W)

    const int bid  = blockIdx.x;
    const bool is_k = bid >= 128;
    const int rb   = bid & 127;
    const float* __restrict__ W = is_k ? Wx : Wt;
    const int t    = threadIdx.x;
    const int row0 = rb * 16;

    const int quad = t & 15;
    const int rg   = t >> 4;

    const float4* __restrict__ Xa = reinterpret_cast<const float4*>(X + (row0+rg  )*D_);
    const float4* __restrict__ Xb = reinterpret_cast<const float4*>(X + (row0+rg+8)*D_);
    const float4* __restrict__ W4 = reinterpret_cast<const float4*>(W);

    unsigned long long a01_0 = 0ull, a23_0 = 0ull;
    unsigned long long a01_1 = 0ull, a23_1 = 0ull;

    #pragma unroll
    for (int half = 0; half < 2; ++half) {
        __syncthreads();
        #pragma unroll
        for (int i = 0; i < 16; ++i)
            reinterpret_cast<float4*>(W_s)[t + i*128] = W4[half*2048 + t + i*128];
        __syncthreads();

        const int dbase = half * 32;
        #pragma unroll 4
        for (int d4 = 0; d4 < 32; ++d4) {
            float4 xa = Xa[dbase + d4];
            float4 xb = Xb[dbase + d4];
            const float* xaf = reinterpret_cast<const float*>(&xa);
            const float* xbf = reinterpret_cast<const float*>(&xb);
            #pragma unroll
            for (int c = 0; c < 4; ++c) {
                ulonglong2 w2 = *reinterpret_cast<const ulonglong2*>(W_s + (d4*4+c)*U_ + quad*4);
                unsigned long long xx0 = dup2(xaf[c]);
                unsigned long long xx1 = dup2(xbf[c]);
                fma2(a01_0, xx0, w2.x);
                fma2(a23_0, xx0, w2.y);
                fma2(a01_1, xx1, w2.x);
                fma2(a23_1, xx1, w2.y);
            }
        }
    }

    float bx = 0.f, by = 0.f, bz = 0.f, bw = 0.f;
    if (is_k) { bx = bh[quad*4+0]; by = bh[quad*4+1]; bz = bh[quad*4+2]; bw = bh[quad*4+3]; }

    float* base = (is_k ? g_k : g_q);
    {
        float2 v01 = unpack2(a01_0), v23 = unpack2(a23_0);
        float4 o; o.x = v01.x+bx; o.y = v01.y+by; o.z = v23.x+bz; o.w = v23.y+bw;
        *reinterpret_cast<float4*>(base + (row0 + rg)*U_ + quad*4) = o;
    }
    {
        float2 v01 = unpack2(a01_1), v23 = unpack2(a23_1);
        float4 o; o.x = v01.x+bx; o.y = v01.y+by; o.z = v23.x+bz; o.w = v23.y+bw;
        *reinterpret_cast<float4*>(base + (row0 + rg + 8)*U_ + quad*4) = o;
    }
}

// ---------------------------------------------------------------------------
// Phase 2: split-KV dual-group attention, TJ=64 (R15 = measured best),
// with 2 barriers/tile: wait(k) -> barg -> commit X(n)+k(n+1) -> score
// (X fill hides under score) -> store p -> wait(X) -> barg -> sum+PV.
// PV is the R15 form (dp-mapped, p4 row-major broadcast reads).
// ---------------------------------------------------------------------------
#define GRP_B (32768 + 65536)      // kbuf 2x16KB + Xs 64KB

__global__ void __launch_bounds__(512, 1) attn_kernel(
    const float* __restrict__ X, const float* __restrict__ Wa,
    float* __restrict__ out)
{
    extern __shared__ __align__(16) unsigned char smem_raw[];

    const int t    = threadIdx.x;
    const int g    = t >> 8;           // group 0/1
    const int tl   = t & 255;          // thread-in-group
    const int lane = t & 31;
    const int wl   = (t >> 5) & 7;     // warp-in-group = row
    const int b    = blockIdx.x >> 5;
    const int pr   = blockIdx.x & 31;

    const int i0A  = pr * TI;
    const int i0B  = (63 - pr) * TI;
    const int ntjA = pr/8 + 1;             // A tiles (1..4)
    const int sB   = 5 - ntjA;             // group0's B tiles [0, sB)
    const int njobs = g ? 4 : 5;

    unsigned char* grp = smem_raw + g*GRP_B;
    float4* kbuf = reinterpret_cast<float4*>(grp);                 // 2x16KB
    float*  Xs   = reinterpret_cast<float*>(grp + 32768);          // 64KB [j][d]
    unsigned char* tail = smem_raw + 2*GRP_B;
    float4* q_all  = reinterpret_cast<float4*>(tail);              // 4KB
    float4* wa4    = reinterpret_cast<float4*>(tail + 4096);       // 256B
    float*  p4     = reinterpret_cast<float*>(tail + 4352) + g*512;   // 2x2KB
    float*  alpha_s= reinterpret_cast<float*>(tail + 8448) + g*8;
    float*  sinv   = reinterpret_cast<float*>(tail + 8512) + g*8;
    float*  paccb  = reinterpret_cast<float*>(tail + 8576);        // 2x8KB
    float*  pacc   = paccb + g*2048;
    float*  pmb    = reinterpret_cast<float*>(tail + 8576 + 16384);
    float*  psb    = pmb + 16;
    float*  pm     = pmb + g*8;
    float*  ps     = psb + g*8;

    const float* __restrict__ Xb = X   + b*L_*D_;
    const float* __restrict__ kb = g_k + b*L_*U_;
    const float* __restrict__ qb = g_q + b*L_*U_;

    if (t < U_) reinterpret_cast<float*>(wa4)[t] = Wa[t] * 1.4426950408889634f;
    if (t < 256) {                         // q for both row-tiles (16 rows)
        int rt = t >> 7, idx = t & 127;
        int i = idx >> 4, uq = idx & 15;
        int gr = (rt ? i0B : i0A) + i;
        q_all[rt*128 + uq*8 + i] = *reinterpret_cast<const float4*>(qb + gr*U_ + uq*4);
    }

    // cp.async targets
    const unsigned k_base = smem_u32(kbuf);
    const unsigned x_dst0 = smem_u32(Xs) + tl*16;
    const unsigned KBUF_B = 1024*16;   // 16KB per buffer

    const int dp  = tl & 127;
    const int ih  = tl >> 7;
    const int ib0 = ih * 4;
    const int bid_bar = 1 + g;

    // prologue: prefetch k(job 0) into buffer 0
    {
        const int j0p = g ? sB*TJ : 0;
        #pragma unroll
        for (int rep = 0; rep < 4; ++rep) {
            int idx = tl + rep*256;
            int uq = idx & 15, j = idx >> 4;
            cp16(k_base + (uq*TJ + j)*16, kb + (j0p + j)*U_ + uq*4);
        }
        cp_commit();
    }
    __syncthreads();   // wa4 + q_all visible CTA-wide

    float m_run = -1e30f, s_run = 0.f;
    unsigned long long acc[4] = {0ull, 0ull, 0ull, 0ull};

    for (int n = 0; n < njobs; ++n) {
        // decode job -> (row-tile rt, j0)
        int rt, j0;
        if (g == 0) {
            if (n < ntjA) { rt = 0; j0 = n*TJ; }
            else          { rt = 1; j0 = (n - ntjA)*TJ; }
        } else            { rt = 1; j0 = (sB + n)*TJ; }
        const int cur = n & 1;
        const bool more = (n + 1 < njobs);

        cp_wait0();      // k(n) landed (only k pending at loop top)
        barg(bid_bar);   // k(n) visible + prev PV done reading Xs/p4

        // commit X(n) fill (64KB: 16 cp16/thread) -- hides under score below
        #pragma unroll
        for (int rep = 0; rep < 16; ++rep) {
            int idx = tl + rep*256;
            cp16(x_dst0 + rep*4096, Xb + (j0 + (idx>>6))*D_ + (idx&63)*4);
        }
        cp_commit();
        // commit k(n+1) fill
        if (more) {
            int j0n;
            if (g == 0) j0n = (n+1 < ntjA) ? (n+1)*TJ : (n+1-ntjA)*TJ;
            else        j0n = (sB + n + 1)*TJ;
            const unsigned off = ((n+1) & 1)*KBUF_B;
            #pragma unroll
            for (int rep = 0; rep < 4; ++rep) {
                int idx = tl + rep*256;
                int uq = idx & 15, j = idx >> 4;
                cp16(k_base + off + (uq*TJ + j)*16, kb + (j0n + j)*U_ + uq*4);
            }
            cp_commit();
        }

        // ---- score: rows wl, j = j0+lane and j0+lane+32, log2 domain ----
        const int gi = (rt ? i0B : i0A) + wl;
        const float4* kc = kbuf + cur*1024;
        const float4* qr = q_all + rt*128;
        float e0 = 0.f, e1 = 0.f, e2 = 0.f, e3 = 0.f;
        #pragma unroll
        for (int uq = 0; uq < 16; ++uq) {
            float4 kv0 = kc[uq*TJ + lane];        // conflict-free
            float4 kv1 = kc[uq*TJ + lane + 32];   // conflict-free
            float4 qv  = qr[uq*8 + wl];           // broadcast
            float4 wa  = wa4[uq];                 // broadcast
            e0 += wa.x * tanh_ap(qv.x + kv0.x);
            e1 += wa.y * tanh_ap(qv.y + kv0.y);
            e0 += wa.z * tanh_ap(qv.z + kv0.z);
            e1 += wa.w * tanh_ap(qv.w + kv0.w);
            e2 += wa.x * tanh_ap(qv.x + kv1.x);
            e3 += wa.y * tanh_ap(qv.y + kv1.y);
            e2 += wa.z * tanh_ap(qv.z + kv1.z);
            e3 += wa.w * tanh_ap(qv.w + kv1.w);
        }
        float eA = e0 + e1;
        float eB = e2 + e3;
        if (j0 + lane      > gi) eA = -1e30f;   // causal: exp2 -> exact 0
        if (j0 + lane + 32 > gi) eB = -1e30f;

        // ---- max reduce + p (sum deferred past barrier) ----
        float mt = fmaxf(eA, eB);
        #pragma unroll
        for (int off = 16; off; off >>= 1)
            mt = fmaxf(mt, __shfl_xor_sync(0xffffffffu, mt, off));
        float m_new = fmaxf(m_run, mt);
        float p0 = ex2_ap(eA - m_new);
        float p1 = ex2_ap(eB - m_new);
        float alpha = ex2_ap(m_run - m_new);
        p4[wl*TJ + lane]      = p0;
        p4[wl*TJ + lane + 32] = p1;
        if (lane == 0) alpha_s[wl] = alpha;

        if (more) cp_wait1(); else cp_wait0();   // X(n) landed (k(n+1) may pend)
        barg(bid_bar);                           // X + p4 + alpha visible

        // deferred sum reduction (overlaps PV issue below)
        float st = p0 + p1;
        #pragma unroll
        for (int off = 16; off; off >>= 1)
            st += __shfl_xor_sync(0xffffffffu, st, off);
        s_run = s_run * alpha + st;
        m_run = m_new;

        // ---- PV update (R15 inner form) ----
        #pragma unroll
        for (int i = 0; i < 4; ++i)
            mul2(acc[i], dup2(alpha_s[ib0+i]));

        const unsigned long long* xcol =
            reinterpret_cast<const unsigned long long*>(Xs) + dp;
        #pragma unroll
        for (int jc = 0; jc < TJ/4; ++jc) {
            unsigned long long xv0 = xcol[(jc*4+0)*(D_/2)];
            unsigned long long xv1 = xcol[(jc*4+1)*(D_/2)];
            unsigned long long xv2 = xcol[(jc*4+2)*(D_/2)];
            unsigned long long xv3 = xcol[(jc*4+3)*(D_/2)];
            float4 pv[4];
            #pragma unroll
            for (int i = 0; i < 4; ++i)
                pv[i] = *reinterpret_cast<const float4*>(&p4[(ib0+i)*TJ + jc*4]); // broadcast
            #pragma unroll
            for (int i = 0; i < 4; ++i) {
                const float* pf = reinterpret_cast<const float*>(&pv[i]);
                fma2(acc[i], xv0, dup2(pf[0]));
                fma2(acc[i], xv1, dup2(pf[1]));
                fma2(acc[i], xv2, dup2(pf[2]));
                fma2(acc[i], xv3, dup2(pf[3]));
            }
        }

        // ---- segment boundaries ----
        const bool direct = (g == 0) && (n + 1 == ntjA);
        if (direct) {
            if (lane == 0) sinv[wl] = 1.0f / s_run;
            barg(bid_bar);              // sinv visible (only on the direct tile)
            #pragma unroll
            for (int i = 0; i < 4; ++i) {
                float2 v = unpack2(acc[i]);
                float is = sinv[ib0 + i];
                *reinterpret_cast<float2*>(out + (b*L_ + i0A + ib0 + i)*D_ + dp*2)
                    = make_float2(v.x*is, v.y*is);
                acc[i] = 0ull;
            }
            m_run = -1e30f; s_run = 0.f;
        } else if (n + 1 == njobs) {
            // flush B partial (unnormalized acc + m,s) for merge
            if (lane == 0) { pm[wl] = m_run; ps[wl] = s_run; }
            #pragma unroll
            for (int i = 0; i < 4; ++i) {
                float2 v = unpack2(acc[i]);
                *reinterpret_cast<float2*>(&pacc[(ib0+i)*D_ + dp*2]) = v;
            }
        }
        // next iteration's top barg orders Xs/p4 reuse
    }

    // ---- merge the two B partials (flash-decoding combine) ----
    __syncthreads();
    {
        const int r  = t >> 6;   // 0..7
        const int dq = t & 63;   // d-quad
        float m0 = pmb[r],  m1 = pmb[8 + r];
        float s0 = psb[r],  s1 = psb[8 + r];
        float M  = fmaxf(m0, m1);
        float w0 = ex2_ap(m0 - M), w1 = ex2_ap(m1 - M);
        float dn = 1.0f / (w0*s0 + w1*s1);
        float4 a0 = *reinterpret_cast<float4*>(&paccb[r*D_ + dq*4]);
        float4 a1 = *reinterpret_cast<float4*>(&paccb[2048 + r*D_ + dq*4]);
        float4 o;
        o.x = (w0*a0.x + w1*a1.x)*dn;
        o.y = (w0*a0.y + w1*a1.y)*dn;
        o.z = (w0*a0.z + w1*a1.z)*dn;
        o.w = (w0*a0.w + w1*a1.w)*dn;
        *reinterpret_cast<float4*>(out + (b*L_ + i0B + r)*D_ + dq*4) = o;
    }
}

// ---------------------------------------------------------------------------
extern "C" void kernel_launch(void* const* d_in, const int* in_sizes, int n_in,
                              void* d_out, int out_size)
{
    const float* X  = (const float*)d_in[0];
    const float* Wt = (const float*)d_in[1];
    const float* Wx = (const float*)d_in[2];
    const float* bh = (const float*)d_in[3];
    const float* Wa = (const float*)d_in[4];
    // d_in[5] = ba : constant shift inside softmax -> mathematically a no-op

    const int attn_smem = 2*GRP_B + 25088;   // ~216.5KB
    cudaFuncSetAttribute(attn_kernel, cudaFuncAttributeMaxDynamicSharedMemorySize, attn_smem);

    proj_kernel<<<256, 128>>>(X, Wt, Wx, bh);
    attn_kernel<<<B_*(NTROW/2), 512, attn_smem>>>(X, Wa, (float*)d_out);
}